// round 1
// baseline (speedup 1.0000x reference)
#include <cuda_runtime.h>
#include <cuda_bf16.h>
#include <cstddef>

// Problem constants (from reference): D=768, NINS=64, H=64 hidden.
#define DD    768
#define NINS  64
#define HH    64
#define LDX   772   // 768 + 4 pad (floats) to avoid smem bank conflicts

// smem layout (floats):
//   Xs   : NINS*LDX        = 49408
//   own  : DD              = 768
//   cvec : HH              = 64
//   w2s  : HH              = 64
//   attv : HH              = 64
//   wts  : HH              = 64
//   red  : 4*HH            = 256
#define SMEM_FLOATS (NINS*LDX + DD + 4*HH + 4*HH)
#define SMEM_BYTES  (SMEM_FLOATS * 4)

typedef unsigned long long ull;

__device__ __forceinline__ ull pack2(float lo, float hi) {
    ull r;
    asm("mov.b64 %0, {%1,%2};" : "=l"(r) : "f"(lo), "f"(hi));
    return r;
}
__device__ __forceinline__ void unpack2(ull v, float& lo, float& hi) {
    asm("mov.b64 {%0,%1}, %2;" : "=f"(lo), "=f"(hi) : "l"(v));
}
__device__ __forceinline__ ull fma2(ull a, ull b, ull c) {
    ull d;
    asm("fma.rn.f32x2 %0, %1, %2, %3;" : "=l"(d) : "l"(a), "l"(b), "l"(c));
    return d;
}

__global__ __launch_bounds__(256)
void fused_attn_kernel(const float* __restrict__ inputs,
                       const float* __restrict__ claims,
                       const float* __restrict__ W1,
                       const float* __restrict__ b1,
                       const float* __restrict__ W2,
                       const float* __restrict__ b2,
                       const int*   __restrict__ indexp,
                       float*       __restrict__ out)
{
    extern __shared__ float sm[];
    float* Xs     = sm;                      // [NINS][LDX]
    float* ownbuf = Xs + NINS * LDX;         // [DD]
    float* cvec   = ownbuf + DD;             // [HH]
    float* w2s    = cvec + HH;               // [HH]
    float* attv   = w2s + HH;                // [HH]
    float* wts    = attv + HH;               // [HH]
    float* red    = wts + HH;                // [4*HH]

    const int b   = blockIdx.x;
    const int tid = threadIdx.x;

    const float* Xg = inputs + (size_t)b * NINS * DD;

    // ---- Phase 1: load X tile into smem (float4, coalesced) ----
    {
        const float4* src = (const float4*)Xg;
        const int total = NINS * DD / 4;  // 12288
        #pragma unroll 4
        for (int i = tid; i < total; i += 256) {
            int n  = i / (DD / 4);
            int k4 = i - n * (DD / 4);
            float4 v = __ldg(src + i);
            *(float4*)(Xs + n * LDX + 4 * k4) = v;
        }
    }

    const int index = __ldg(indexp);
    if (index <= -1) {
        const float4* csrc = (const float4*)(claims + (size_t)b * DD);
        for (int i = tid; i < DD / 4; i += 256) {
            float4 v = __ldg(csrc + i);
            *(float4*)(ownbuf + 4 * i) = v;
        }
    }
    if (tid < HH) w2s[tid] = __ldg(W2 + tid);
    __syncthreads();

    const float* ownrow = (index > -1) ? (Xs + index * LDX) : ownbuf;

    // ---- Phase 2: cvec[j] = own . W1a[:,j] + b1[j]  (k split 4 ways) ----
    {
        const int part = tid >> 6;       // 0..3
        const int j    = tid & 63;
        const int kbeg = part * (DD / 4);  // 192 k's each
        const float* wa = W1 + j;
        float a0 = 0.f, a1 = 0.f, a2 = 0.f, a3 = 0.f;
        #pragma unroll 4
        for (int k = kbeg; k < kbeg + DD / 4; k += 4) {
            a0 = fmaf(ownrow[k + 0], __ldg(wa + (size_t)(k + 0) * HH), a0);
            a1 = fmaf(ownrow[k + 1], __ldg(wa + (size_t)(k + 1) * HH), a1);
            a2 = fmaf(ownrow[k + 2], __ldg(wa + (size_t)(k + 2) * HH), a2);
            a3 = fmaf(ownrow[k + 3], __ldg(wa + (size_t)(k + 3) * HH), a3);
        }
        red[tid] = (a0 + a1) + (a2 + a3);
    }
    __syncthreads();
    if (tid < HH) {
        cvec[tid] = red[tid] + red[tid + 64] + red[tid + 128] + red[tid + 192]
                  + __ldg(b1 + tid);
    }
    __syncthreads();

    // ---- Phase 3: main GEMM  acc[n][j] = sum_k X[n][k] * W1b[k][j] ----
    // Thread (ng,jg) computes a 4n x 4j register tile; f32x2 packed FMA.
    const int jg = tid & 15;
    const int ng = tid >> 4;
    const int j0 = jg << 2;
    const int n0 = ng << 2;

    const float* Wb   = W1 + (size_t)DD * HH + j0;  // W1b rows, this thread's 4 cols
    const float* xrow = Xs + n0 * LDX;

    ull acc[4][2];
    #pragma unroll
    for (int i = 0; i < 4; i++) { acc[i][0] = 0ull; acc[i][1] = 0ull; }

    const int KU = 8;
    #pragma unroll 1
    for (int k = 0; k < DD; k += KU) {
        float4 wreg[KU];
        #pragma unroll
        for (int u = 0; u < KU; u++)
            wreg[u] = __ldg((const float4*)(Wb + (size_t)(k + u) * HH));
        #pragma unroll
        for (int u = 0; u < KU; u++) {
            ull w01 = pack2(wreg[u].x, wreg[u].y);
            ull w23 = pack2(wreg[u].z, wreg[u].w);
            #pragma unroll
            for (int i = 0; i < 4; i++) {
                float xv = xrow[i * LDX + k + u];
                ull xx = pack2(xv, xv);
                acc[i][0] = fma2(xx, w01, acc[i][0]);
                acc[i][1] = fma2(xx, w23, acc[i][1]);
            }
        }
    }

    // ---- Phase 4: epilogue  att[n] = sum_j relu(acc + cvec[j]) * W2[j] ----
    {
        float c0 = cvec[j0 + 0], c1 = cvec[j0 + 1], c2 = cvec[j0 + 2], c3 = cvec[j0 + 3];
        float v0 = w2s[j0 + 0],  v1 = w2s[j0 + 1],  v2 = w2s[j0 + 2],  v3 = w2s[j0 + 3];
        #pragma unroll
        for (int i = 0; i < 4; i++) {
            float h0, h1, h2, h3;
            unpack2(acc[i][0], h0, h1);
            unpack2(acc[i][1], h2, h3);
            h0 = fmaxf(h0 + c0, 0.f);
            h1 = fmaxf(h1 + c1, 0.f);
            h2 = fmaxf(h2 + c2, 0.f);
            h3 = fmaxf(h3 + c3, 0.f);
            float ap = h0 * v0 + h1 * v1 + h2 * v2 + h3 * v3;
            // reduce across the 16 jg lanes (lane bits 0..3)
            #pragma unroll
            for (int off = 8; off > 0; off >>= 1)
                ap += __shfl_xor_sync(0xffffffffu, ap, off);
            if (jg == 0) attv[n0 + i] = ap;
        }
    }
    __syncthreads();

    // ---- Phase 5: softmax over 64 instances (single warp) ----
    if (tid < 32) {
        float a0 = attv[tid], a1 = attv[tid + 32];
        float m = fmaxf(a0, a1);
        #pragma unroll
        for (int off = 16; off > 0; off >>= 1)
            m = fmaxf(m, __shfl_xor_sync(0xffffffffu, m, off));
        float e0 = expf(a0 - m), e1 = expf(a1 - m);
        float s = e0 + e1;
        #pragma unroll
        for (int off = 16; off > 0; off >>= 1)
            s += __shfl_xor_sync(0xffffffffu, s, off);
        float inv = 1.0f / s;
        wts[tid]      = e0 * inv;
        wts[tid + 32] = e1 * inv;
    }
    __syncthreads();

    // ---- Phase 6: pooling  out[b][d] = sum_n wts[n] * X[n][d] ----
    if (tid < DD / 4) {  // 192 threads, one float4 column each
        float4 a = make_float4(0.f, 0.f, 0.f, 0.f);
        const float* xcol = Xs + 4 * tid;
        #pragma unroll 8
        for (int n = 0; n < NINS; n++) {
            float wn = wts[n];
            float4 xv = *(const float4*)(xcol + n * LDX);
            a.x = fmaf(wn, xv.x, a.x);
            a.y = fmaf(wn, xv.y, a.y);
            a.z = fmaf(wn, xv.z, a.z);
            a.w = fmaf(wn, xv.w, a.w);
        }
        *(float4*)(out + (size_t)b * DD + 4 * tid) = a;
    }
}

extern "C" void kernel_launch(void* const* d_in, const int* in_sizes, int n_in,
                              void* d_out, int out_size)
{
    const float* inputs = (const float*)d_in[0];
    const float* claims = (const float*)d_in[1];
    const float* W1     = (const float*)d_in[2];
    const float* b1     = (const float*)d_in[3];
    const float* W2     = (const float*)d_in[4];
    const float* b2     = (const float*)d_in[5];
    const int*   indexp = (const int*)d_in[6];
    float*       out    = (float*)d_out;

    const int B = in_sizes[0] / (NINS * DD);

    cudaFuncSetAttribute(fused_attn_kernel,
                         cudaFuncAttributeMaxDynamicSharedMemorySize, SMEM_BYTES);
    fused_attn_kernel<<<B, 256, SMEM_BYTES>>>(inputs, claims, W1, b1, W2, b2,
                                              indexp, out);
}

// round 2
// speedup vs baseline: 1.5646x; 1.5646x over previous
#include <cuda_runtime.h>
#include <cuda_bf16.h>
#include <cstddef>

#define DD    768
#define NINS  64
#define HH    64
#define LDX   772   // 768 + 4 pad floats
#define NKG   (DD / 8)   // 96 k-groups of 8

#define SMEM_FLOATS (NINS*LDX + DD + 4*HH + 4*HH)
#define SMEM_BYTES  (SMEM_FLOATS * 4)

typedef unsigned long long ull;

__device__ __forceinline__ ull pack2(float lo, float hi) {
    ull r;
    asm("mov.b64 %0, {%1,%2};" : "=l"(r) : "f"(lo), "f"(hi));
    return r;
}
__device__ __forceinline__ void unpack2(ull v, float& lo, float& hi) {
    asm("mov.b64 {%0,%1}, %2;" : "=f"(lo), "=f"(hi) : "l"(v));
}
__device__ __forceinline__ ull fma2(ull a, ull b, ull c) {
    ull d;
    asm("fma.rn.f32x2 %0, %1, %2, %3;" : "=l"(d) : "l"(a), "l"(b), "l"(c));
    return d;
}

// Prefetch one k-group (8 rows) of this thread's 4 W columns, as packed pairs.
__device__ __forceinline__ void pf_group(ulonglong2 (&wb)[8],
                                         const float* __restrict__ Wcol,
                                         int kbase) {
    #pragma unroll
    for (int u = 0; u < 8; u++)
        wb[u] = __ldg((const ulonglong2*)(Wcol + (size_t)(kbase + u) * HH));
}

// One k-group of FMAs: 2 n-rows x 4 j-cols, 8 k-steps.
__device__ __forceinline__ void compute_group(const ulonglong2 (&wb)[8],
                                              const float* __restrict__ x0,
                                              const float* __restrict__ x1,
                                              int k, ull (&acc)[2][2]) {
    float4 a0 = *(const float4*)(x0 + k);
    float4 b0 = *(const float4*)(x0 + k + 4);
    float4 a1 = *(const float4*)(x1 + k);
    float4 b1 = *(const float4*)(x1 + k + 4);
    float xr0[8] = {a0.x, a0.y, a0.z, a0.w, b0.x, b0.y, b0.z, b0.w};
    float xr1[8] = {a1.x, a1.y, a1.z, a1.w, b1.x, b1.y, b1.z, b1.w};
    #pragma unroll
    for (int u = 0; u < 8; u++) {
        ull xx0 = pack2(xr0[u], xr0[u]);
        ull xx1 = pack2(xr1[u], xr1[u]);
        acc[0][0] = fma2(xx0, wb[u].x, acc[0][0]);
        acc[0][1] = fma2(xx0, wb[u].y, acc[0][1]);
        acc[1][0] = fma2(xx1, wb[u].x, acc[1][0]);
        acc[1][1] = fma2(xx1, wb[u].y, acc[1][1]);
    }
}

__global__ __launch_bounds__(512, 1)
void fused_attn_kernel(const float* __restrict__ inputs,
                       const float* __restrict__ claims,
                       const float* __restrict__ W1,
                       const float* __restrict__ b1,
                       const float* __restrict__ W2,
                       const float* __restrict__ b2,
                       const int*   __restrict__ indexp,
                       float*       __restrict__ out)
{
    extern __shared__ float sm[];
    float* Xs     = sm;                      // [NINS][LDX]
    float* ownbuf = Xs + NINS * LDX;         // [DD]
    float* cvec   = ownbuf + DD;             // [HH]
    float* w2s    = cvec + HH;               // [HH]
    float* attv   = w2s + HH;                // [HH]
    float* wts    = attv + HH;               // [HH]
    float* red    = wts + HH;                // [4*HH]

    const int b   = blockIdx.x;
    const int tid = threadIdx.x;

    const float* Xg = inputs + (size_t)b * NINS * DD;

    // ---- Phase 1: load X tile into smem ----
    {
        const float4* src = (const float4*)Xg;
        const int total = NINS * DD / 4;  // 12288; 24 per thread
        #pragma unroll 6
        for (int i = tid; i < total; i += 512) {
            int n  = i / (DD / 4);
            int k4 = i - n * (DD / 4);
            float4 v = __ldg(src + i);
            *(float4*)(Xs + n * LDX + 4 * k4) = v;
        }
    }

    const int index = __ldg(indexp);
    if (index <= -1) {
        const float4* csrc = (const float4*)(claims + (size_t)b * DD);
        for (int i = tid; i < DD / 4; i += 512) {
            float4 v = __ldg(csrc + i);
            *(float4*)(ownbuf + 4 * i) = v;
        }
    }
    if (tid < HH) w2s[tid] = __ldg(W2 + tid);
    __syncthreads();

    const float* ownrow = (index > -1) ? (Xs + index * LDX) : ownbuf;

    // ---- Phase 2: cvec[j] = own . W1a[:,j] + b1[j]  (k split 4 ways, 256 threads) ----
    if (tid < 256) {
        const int part = tid >> 6;
        const int j    = tid & 63;
        const int kbeg = part * (DD / 4);
        const float* wa = W1 + j;
        float a0 = 0.f, a1 = 0.f, a2 = 0.f, a3 = 0.f;
        #pragma unroll 4
        for (int k = kbeg; k < kbeg + DD / 4; k += 4) {
            a0 = fmaf(ownrow[k + 0], __ldg(wa + (size_t)(k + 0) * HH), a0);
            a1 = fmaf(ownrow[k + 1], __ldg(wa + (size_t)(k + 1) * HH), a1);
            a2 = fmaf(ownrow[k + 2], __ldg(wa + (size_t)(k + 2) * HH), a2);
            a3 = fmaf(ownrow[k + 3], __ldg(wa + (size_t)(k + 3) * HH), a3);
        }
        red[tid] = (a0 + a1) + (a2 + a3);
    }
    __syncthreads();
    if (tid < HH) {
        cvec[tid] = red[tid] + red[tid + 64] + red[tid + 128] + red[tid + 192]
                  + __ldg(b1 + tid);
    }
    __syncthreads();

    // ---- Phase 3: main GEMM  acc[n][j] = sum_k X[n][k] * W1b[k][j] ----
    // 512 threads: jg in [0,16) -> 4 j-cols, ng in [0,32) -> 2 n-rows.
    const int jg = tid & 15;
    const int ng = tid >> 4;
    const int j0 = jg << 2;
    const int n0 = ng << 1;

    const float* Wcol = W1 + (size_t)DD * HH + j0;   // W1b, this thread's 4 cols
    const float* x0   = Xs + (size_t)n0 * LDX;
    const float* x1   = x0 + LDX;

    ull acc[2][2];
    acc[0][0] = acc[0][1] = acc[1][0] = acc[1][1] = 0ull;

    ulonglong2 wb0[8], wb1[8];
    pf_group(wb0, Wcol, 0);
    pf_group(wb1, Wcol, 8);

    #pragma unroll 1
    for (int kg = 0; kg < NKG; kg += 2) {
        const int k0 = kg * 8;
        const int kn0 = (kg + 2 < NKG) ? (kg + 2) * 8 : 0;  // clamp: valid dummy
        const int kn1 = (kg + 3 < NKG) ? (kg + 3) * 8 : 0;
        compute_group(wb0, x0, x1, k0, acc);
        pf_group(wb0, Wcol, kn0);
        compute_group(wb1, x0, x1, k0 + 8, acc);
        pf_group(wb1, Wcol, kn1);
    }

    // ---- Phase 4: epilogue  att[n] = sum_j relu(acc + cvec[j]) * W2[j] ----
    {
        float c0 = cvec[j0 + 0], c1 = cvec[j0 + 1], c2 = cvec[j0 + 2], c3 = cvec[j0 + 3];
        float v0 = w2s[j0 + 0],  v1 = w2s[j0 + 1],  v2 = w2s[j0 + 2],  v3 = w2s[j0 + 3];
        #pragma unroll
        for (int i = 0; i < 2; i++) {
            float h0, h1, h2, h3;
            unpack2(acc[i][0], h0, h1);
            unpack2(acc[i][1], h2, h3);
            h0 = fmaxf(h0 + c0, 0.f);
            h1 = fmaxf(h1 + c1, 0.f);
            h2 = fmaxf(h2 + c2, 0.f);
            h3 = fmaxf(h3 + c3, 0.f);
            float ap = h0 * v0 + h1 * v1 + h2 * v2 + h3 * v3;
            #pragma unroll
            for (int off = 8; off > 0; off >>= 1)
                ap += __shfl_xor_sync(0xffffffffu, ap, off);
            if (jg == 0) attv[n0 + i] = ap;
        }
    }
    __syncthreads();

    // ---- Phase 5: softmax over 64 instances (single warp) ----
    if (tid < 32) {
        float a0 = attv[tid], a1 = attv[tid + 32];
        float m = fmaxf(a0, a1);
        #pragma unroll
        for (int off = 16; off > 0; off >>= 1)
            m = fmaxf(m, __shfl_xor_sync(0xffffffffu, m, off));
        float e0 = expf(a0 - m), e1 = expf(a1 - m);
        float s = e0 + e1;
        #pragma unroll
        for (int off = 16; off > 0; off >>= 1)
            s += __shfl_xor_sync(0xffffffffu, s, off);
        float inv = 1.0f / s;
        wts[tid]      = e0 * inv;
        wts[tid + 32] = e1 * inv;
    }
    __syncthreads();

    // ---- Phase 6: pooling  out[b][d] = sum_n wts[n] * X[n][d] ----
    if (tid < DD / 4) {  // 192 threads, one float4 column each
        float4 a = make_float4(0.f, 0.f, 0.f, 0.f);
        const float* xcol = Xs + 4 * tid;
        #pragma unroll 8
        for (int n = 0; n < NINS; n++) {
            float wn = wts[n];
            float4 xv = *(const float4*)(xcol + (size_t)n * LDX);
            a.x = fmaf(wn, xv.x, a.x);
            a.y = fmaf(wn, xv.y, a.y);
            a.z = fmaf(wn, xv.z, a.z);
            a.w = fmaf(wn, xv.w, a.w);
        }
        *(float4*)(out + (size_t)b * DD + 4 * tid) = a;
    }
}

extern "C" void kernel_launch(void* const* d_in, const int* in_sizes, int n_in,
                              void* d_out, int out_size)
{
    const float* inputs = (const float*)d_in[0];
    const float* claims = (const float*)d_in[1];
    const float* W1     = (const float*)d_in[2];
    const float* b1     = (const float*)d_in[3];
    const float* W2     = (const float*)d_in[4];
    const float* b2     = (const float*)d_in[5];
    const int*   indexp = (const int*)d_in[6];
    float*       out    = (float*)d_out;

    const int B = in_sizes[0] / (NINS * DD);

    cudaFuncSetAttribute(fused_attn_kernel,
                         cudaFuncAttributeMaxDynamicSharedMemorySize, SMEM_BYTES);
    fused_attn_kernel<<<B, 512, SMEM_BYTES>>>(inputs, claims, W1, b1, W2, b2,
                                              indexp, out);
}

// round 3
// speedup vs baseline: 2.0916x; 1.3368x over previous
#include <cuda_runtime.h>
#include <cuda_bf16.h>
#include <cstddef>

#define DD    768
#define NINS  64
#define HH    64
#define LDX   772        // 768 + 4 pad floats
#define KHALF (DD / 2)   // 384
#define NKG   (KHALF / 8)  // 48 groups of 8 per k-half

// smem: Xs + ownbuf + cvec/w2s/attv/wts + red + part
#define SMEM_FLOATS (NINS*LDX + DD + 4*HH + 4*HH + 256*16)
#define SMEM_BYTES  (SMEM_FLOATS * 4)

typedef unsigned long long ull;

__device__ __forceinline__ ull pack2(float lo, float hi) {
    ull r;
    asm("mov.b64 %0, {%1,%2};" : "=l"(r) : "f"(lo), "f"(hi));
    return r;
}
__device__ __forceinline__ void unpack2(ull v, float& lo, float& hi) {
    asm("mov.b64 {%0,%1}, %2;" : "=f"(lo), "=f"(hi) : "l"(v));
}
__device__ __forceinline__ ull fma2(ull a, ull b, ull c) {
    ull d;
    asm("fma.rn.f32x2 %0, %1, %2, %3;" : "=l"(d) : "l"(a), "l"(b), "l"(c));
    return d;
}
__device__ __forceinline__ ull add2(ull a, ull b) {
    ull d;
    asm("add.rn.f32x2 %0, %1, %2;" : "=l"(d) : "l"(a), "l"(b));
    return d;
}

// Prefetch one k-group (8 rows) of this thread's 4 W columns (packed pairs).
__device__ __forceinline__ void pf_group(ulonglong2 (&wb)[8],
                                         const float* __restrict__ Wcol,
                                         int kbase) {
    #pragma unroll
    for (int u = 0; u < 8; u++)
        wb[u] = __ldg((const ulonglong2*)(Wcol + (size_t)(kbase + u) * HH));
}

// One k-group of FMAs: 4 n-rows x 4 j-cols, 8 k-steps.
__device__ __forceinline__ void compute_group(const ulonglong2 (&wb)[8],
                                              const float* __restrict__ xr,
                                              int k, ull (&acc)[4][2]) {
    #pragma unroll
    for (int i = 0; i < 4; i++) {
        float4 a = *(const float4*)(xr + (size_t)i * LDX + k);
        float4 b = *(const float4*)(xr + (size_t)i * LDX + k + 4);
        float xs[8] = {a.x, a.y, a.z, a.w, b.x, b.y, b.z, b.w};
        #pragma unroll
        for (int u = 0; u < 8; u++) {
            ull xx = pack2(xs[u], xs[u]);
            acc[i][0] = fma2(xx, wb[u].x, acc[i][0]);
            acc[i][1] = fma2(xx, wb[u].y, acc[i][1]);
        }
    }
}

__global__ __launch_bounds__(512, 1)
void fused_attn_kernel(const float* __restrict__ inputs,
                       const float* __restrict__ claims,
                       const float* __restrict__ W1,
                       const float* __restrict__ b1,
                       const float* __restrict__ W2,
                       const float* __restrict__ b2,
                       const int*   __restrict__ indexp,
                       float*       __restrict__ out)
{
    extern __shared__ float sm[];
    float* Xs     = sm;                      // [NINS][LDX]
    float* ownbuf = Xs + NINS * LDX;         // [DD]
    float* cvec   = ownbuf + DD;             // [HH]
    float* w2s    = cvec + HH;               // [HH]
    float* attv   = w2s + HH;                // [HH]
    float* wts    = attv + HH;               // [HH]
    float* red    = wts + HH;                // [4*HH]
    float* part   = red + 4 * HH;            // [256*16] split-k partials

    const int b   = blockIdx.x;
    const int tid = threadIdx.x;

    const float* Xg = inputs + (size_t)b * NINS * DD;

    // ---- Phase 1: load X tile into smem ----
    {
        const float4* src = (const float4*)Xg;
        const int total = NINS * DD / 4;  // 12288; 24 per thread
        #pragma unroll 6
        for (int i = tid; i < total; i += 512) {
            int n  = i / (DD / 4);
            int k4 = i - n * (DD / 4);
            float4 v = __ldg(src + i);
            *(float4*)(Xs + n * LDX + 4 * k4) = v;
        }
    }

    const int index = __ldg(indexp);
    if (index <= -1) {
        const float4* csrc = (const float4*)(claims + (size_t)b * DD);
        for (int i = tid; i < DD / 4; i += 512) {
            float4 v = __ldg(csrc + i);
            *(float4*)(ownbuf + 4 * i) = v;
        }
    }
    if (tid < HH) w2s[tid] = __ldg(W2 + tid);
    __syncthreads();

    const float* ownrow = (index > -1) ? (Xs + index * LDX) : ownbuf;

    // ---- Phase 2: cvec[j] = own . W1a[:,j] + b1[j]  (256 threads, k split 4) ----
    if (tid < 256) {
        const int prt  = tid >> 6;
        const int j    = tid & 63;
        const int kbeg = prt * (DD / 4);
        const float* wa = W1 + j;
        float a0 = 0.f, a1 = 0.f, a2 = 0.f, a3 = 0.f;
        #pragma unroll 4
        for (int k = kbeg; k < kbeg + DD / 4; k += 4) {
            a0 = fmaf(ownrow[k + 0], __ldg(wa + (size_t)(k + 0) * HH), a0);
            a1 = fmaf(ownrow[k + 1], __ldg(wa + (size_t)(k + 1) * HH), a1);
            a2 = fmaf(ownrow[k + 2], __ldg(wa + (size_t)(k + 2) * HH), a2);
            a3 = fmaf(ownrow[k + 3], __ldg(wa + (size_t)(k + 3) * HH), a3);
        }
        red[tid] = (a0 + a1) + (a2 + a3);
    }
    __syncthreads();
    if (tid < HH) {
        cvec[tid] = red[tid] + red[tid + 64] + red[tid + 128] + red[tid + 192]
                  + __ldg(b1 + tid);
    }
    __syncthreads();

    // ---- Phase 3: split-k GEMM  acc[n][j] = sum_k X[n][k] * W1b[k][j] ----
    // kh in {0,1} picks a k half; within: jg 16 x ng 16 covers 64j x 64n.
    const int kh = tid >> 8;           // 0 or 1
    const int t  = tid & 255;
    const int jg = t & 15;
    const int ng = t >> 4;
    const int j0 = jg << 2;
    const int n0 = ng << 2;
    const int kbeg = kh * KHALF;

    const float* Wcol = W1 + (size_t)DD * HH + (size_t)kbeg * HH + j0;
    const float* xr   = Xs + (size_t)n0 * LDX + kbeg;

    ull acc[4][2];
    #pragma unroll
    for (int i = 0; i < 4; i++) { acc[i][0] = 0ull; acc[i][1] = 0ull; }

    ulonglong2 wb0[8], wb1[8];
    pf_group(wb0, Wcol, 0);
    pf_group(wb1, Wcol, 8);

    #pragma unroll 1
    for (int kg = 0; kg < NKG; kg += 2) {
        const int k0  = kg * 8;
        const int kn0 = (kg + 2 < NKG) ? (kg + 2) * 8 : 0;
        const int kn1 = (kg + 3 < NKG) ? (kg + 3) * 8 : 0;
        compute_group(wb0, xr, k0, acc);
        pf_group(wb0, Wcol, kn0);
        compute_group(wb1, xr, k0 + 8, acc);
        pf_group(wb1, Wcol, kn1);
    }

    // ---- Phase 3b: combine the two k-half partials ----
    if (kh == 1) {
        ull* p = (ull*)(part + (size_t)t * 16);
        #pragma unroll
        for (int i = 0; i < 4; i++) { p[2*i] = acc[i][0]; p[2*i+1] = acc[i][1]; }
    }
    __syncthreads();

    // ---- Phase 4: epilogue (kh==0 threads)  att[n] = sum_j relu(.)*W2[j] ----
    if (kh == 0) {
        const ull* p = (const ull*)(part + (size_t)t * 16);
        float c0 = cvec[j0 + 0], c1 = cvec[j0 + 1], c2 = cvec[j0 + 2], c3 = cvec[j0 + 3];
        float v0 = w2s[j0 + 0],  v1 = w2s[j0 + 1],  v2 = w2s[j0 + 2],  v3 = w2s[j0 + 3];
        #pragma unroll
        for (int i = 0; i < 4; i++) {
            ull s0 = add2(acc[i][0], p[2*i]);
            ull s1 = add2(acc[i][1], p[2*i+1]);
            float h0, h1, h2, h3;
            unpack2(s0, h0, h1);
            unpack2(s1, h2, h3);
            h0 = fmaxf(h0 + c0, 0.f);
            h1 = fmaxf(h1 + c1, 0.f);
            h2 = fmaxf(h2 + c2, 0.f);
            h3 = fmaxf(h3 + c3, 0.f);
            float ap = h0 * v0 + h1 * v1 + h2 * v2 + h3 * v3;
            #pragma unroll
            for (int off = 8; off > 0; off >>= 1)
                ap += __shfl_xor_sync(0xffffffffu, ap, off);
            if (jg == 0) attv[n0 + i] = ap;
        }
    }
    __syncthreads();

    // ---- Phase 5: softmax over 64 instances (single warp) ----
    if (tid < 32) {
        float a0 = attv[tid], a1 = attv[tid + 32];
        float m = fmaxf(a0, a1);
        #pragma unroll
        for (int off = 16; off > 0; off >>= 1)
            m = fmaxf(m, __shfl_xor_sync(0xffffffffu, m, off));
        float e0 = expf(a0 - m), e1 = expf(a1 - m);
        float s = e0 + e1;
        #pragma unroll
        for (int off = 16; off > 0; off >>= 1)
            s += __shfl_xor_sync(0xffffffffu, s, off);
        float inv = 1.0f / s;
        wts[tid]      = e0 * inv;
        wts[tid + 32] = e1 * inv;
    }
    __syncthreads();

    // ---- Phase 6: pooling  out[b][d] = sum_n wts[n] * X[n][d] ----
    // 384 threads: 192 float4 columns x 2 n-halves, combine via part smem.
    if (tid < 384) {
        const int half = tid / 192;          // 0: n 0..31, 1: n 32..63
        const int col  = tid % 192;
        float4 a = make_float4(0.f, 0.f, 0.f, 0.f);
        const float* xcol = Xs + 4 * col + (size_t)half * 32 * LDX;
        const float* wp = wts + half * 32;
        #pragma unroll 8
        for (int n = 0; n < 32; n++) {
            float wn = wp[n];
            float4 xv = *(const float4*)(xcol + (size_t)n * LDX);
            a.x = fmaf(wn, xv.x, a.x);
            a.y = fmaf(wn, xv.y, a.y);
            a.z = fmaf(wn, xv.z, a.z);
            a.w = fmaf(wn, xv.w, a.w);
        }
        if (half == 1) *(float4*)(part + 4 * col) = a;
        __syncthreads();
        if (half == 0) {
            float4 bq = *(const float4*)(part + 4 * col);
            a.x += bq.x; a.y += bq.y; a.z += bq.z; a.w += bq.w;
            *(float4*)(out + (size_t)b * DD + 4 * col) = a;
        }
    } else {
        __syncthreads();
    }
}

extern "C" void kernel_launch(void* const* d_in, const int* in_sizes, int n_in,
                              void* d_out, int out_size)
{
    const float* inputs = (const float*)d_in[0];
    const float* claims = (const float*)d_in[1];
    const float* W1     = (const float*)d_in[2];
    const float* b1     = (const float*)d_in[3];
    const float* W2     = (const float*)d_in[4];
    const float* b2     = (const float*)d_in[5];
    const int*   indexp = (const int*)d_in[6];
    float*       out    = (float*)d_out;

    const int B = in_sizes[0] / (NINS * DD);

    cudaFuncSetAttribute(fused_attn_kernel,
                         cudaFuncAttributeMaxDynamicSharedMemorySize, SMEM_BYTES);
    fused_attn_kernel<<<B, 512, SMEM_BYTES>>>(inputs, claims, W1, b1, W2, b2,
                                              indexp, out);
}